// round 15
// baseline (speedup 1.0000x reference)
#include <cuda_runtime.h>
#include <cuda_bf16.h>

// ---------------- static problem config ----------------
#define BB     2
#define TT     8
#define HHH    64
#define WWW    64
#define CC     128
#define LL     (TT*HHH*WWW)        // 32768
#define NHEAD  4
#define HD     32
#define NTOK   512                 // tokens per window
#define NWIN   128
#define QK_SCALE 0.17677669529663687f   // 1/sqrt(32)
#define LOG2E    1.4426950408889634f

// ---------------- attention smem layout (u32 units) ----------------
#define QK_STRIDE 36                        // 32 + pad -> bank = 4*row+col (conflict-free frags)
#define SK_OFF    0
#define VT_STRIDE 260                       // u32 words per d-row (256 pairs + pad)
#define SVT_OFF   (NTOK*QK_STRIDE)          // 18432
#define SMEM_U32  (SVT_OFF + 32*VT_STRIDE)  // 26752
#define ATTN_SMEM_BYTES (SMEM_U32*4)        // 107008  -> 2 CTAs/SM

// ---------------- helpers ----------------
__device__ __forceinline__ unsigned f2tf32(float x) {
    unsigned r; asm("cvt.rna.tf32.f32 %0, %1;" : "=r"(r) : "f"(x)); return r;
}
__device__ __forceinline__ float ex2f(float x) {
    float r; asm("ex2.approx.ftz.f32 %0, %1;" : "=f"(r) : "f"(x)); return r;
}
__device__ __forceinline__ unsigned pack_bf16x2(float lo, float hi) {
    unsigned r; asm("cvt.rn.bf16x2.f32 %0, %1, %2;" : "=r"(r) : "f"(hi), "f"(lo)); return r;
}
__device__ __forceinline__ void mma_tf32(float c[4], const unsigned a[4], unsigned b0, unsigned b1) {
    asm volatile(
        "mma.sync.aligned.m16n8k8.row.col.f32.tf32.tf32.f32 "
        "{%0,%1,%2,%3},{%4,%5,%6,%7},{%8,%9},{%0,%1,%2,%3};"
        : "+f"(c[0]), "+f"(c[1]), "+f"(c[2]), "+f"(c[3])
        : "r"(a[0]), "r"(a[1]), "r"(a[2]), "r"(a[3]), "r"(b0), "r"(b1));
}
__device__ __forceinline__ void mma_bf16(float c[4], unsigned a0, unsigned a1, unsigned a2, unsigned a3,
                                         unsigned b0, unsigned b1) {
    asm volatile(
        "mma.sync.aligned.m16n8k16.row.col.f32.bf16.bf16.f32 "
        "{%0,%1,%2,%3},{%4,%5,%6,%7},{%8,%9},{%0,%1,%2,%3};"
        : "+f"(c[0]), "+f"(c[1]), "+f"(c[2]), "+f"(c[3])
        : "r"(a0), "r"(a1), "r"(a2), "r"(a3), "r"(b0), "r"(b1));
}

// token n in window -> flattened l (given window coords tB, wB)
__device__ __forceinline__ int token_to_l(int n, int tB, int wB) {
    int t_sp = n >> 8;
    int h_sp = (n >> 2) & 63;
    int w_sp = n & 3;
    return (tB*2 + t_sp)*4096 + h_sp*64 + wB*4 + w_sp;
}

// ==================================================================
// Kernel 1: LePE depthwise conv3d  ->  out = lepe (final layout)
// grid: 1024 = 128 windows x 8 h-tiles (8 rows each) ; block: 256
// ==================================================================
#define LP_HT     8                          // h rows per tile
#define LP_SV_F   (2*(LP_HT+2)*4*128)        // 10240 floats
#define LEPE_SMEM_BYTES ((LP_SV_F + 128*27 + 128)*4)   // 55296

__global__ void __launch_bounds__(256, 4)
lepe_kernel(const float* __restrict__ qkv, const float* __restrict__ wts,
            const float* __restrict__ bias, float* __restrict__ out)
{
    extern __shared__ float smf[];
    float* sv = smf;                 // [t=2][hh=10][w=4][c=128]
    float* sw = smf + LP_SV_F;       // [128][27]
    float* sb = sw + 128*27;         // [128]

    const int widx = blockIdx.x >> 3;
    const int tile = blockIdx.x & 7;
    const int b  = widx >> 6;
    const int tB = (widx >> 4) & 3;
    const int wB = widx & 15;
    const int h0 = tile * LP_HT;
    const int tid = threadIdx.x;

    const float* vg = qkv + 2*(size_t)BB*LL*CC + (size_t)b*LL*CC;

    for (int i = tid; i < 128*27; i += 256) sw[i] = wts[i];
    if (tid < 128) sb[tid] = bias[tid];

    // stage v tile (80 rows: t{2} x hh{10 w/ halo} x w{4}, zero pad)
    {
        int sub = tid & 31;     // float4 within a 128-float row
        int rr  = tid >> 5;     // 8 rows per iteration
        for (int r = rr; r < 2*(LP_HT+2)*4; r += 8) {
            int t   = r / ((LP_HT+2)*4);
            int rem = r % ((LP_HT+2)*4);
            int hh  = rem >> 2;
            int w   = rem & 3;
            int h   = h0 - 1 + hh;
            float4 val = make_float4(0.f, 0.f, 0.f, 0.f);
            if ((unsigned)h < 64u) {
                int gl = (tB*2 + t)*4096 + h*64 + wB*4 + w;
                val = *(const float4*)(vg + (size_t)gl*CC + sub*4);
            }
            *(float4*)(sv + (size_t)r*128 + sub*4) = val;
        }
    }
    __syncthreads();

    const int c = tid & 127;
    const int t = tid >> 7;          // each half-block owns one t slice
    float wr[27];
#pragma unroll
    for (int j = 0; j < 27; ++j) wr[j] = sw[c*27 + j];
    const float bval = sb[c];

    float* outg = out + (size_t)b*LL*CC;

    for (int hl = 0; hl < LP_HT; ++hl) {
        float a0 = bval, a1 = bval, a2 = bval, a3 = bval;
#pragma unroll
        for (int dt = 0; dt < 3; ++dt) {
            int tt = t + dt - 1;
            if ((unsigned)tt >= 2u) continue;
#pragma unroll
            for (int dh = 0; dh < 3; ++dh) {
                const float* base = sv + ((size_t)(tt*(LP_HT+2) + hl + dh)*4)*128 + c;
                float r0 = base[0], r1 = base[128], r2 = base[256], r3 = base[384];
                float w0 = wr[(dt*3+dh)*3+0], w1 = wr[(dt*3+dh)*3+1], w2 = wr[(dt*3+dh)*3+2];
                a0 += w1*r0 + w2*r1;
                a1 += w0*r0 + w1*r1 + w2*r2;
                a2 += w0*r1 + w1*r2 + w2*r3;
                a3 += w0*r2 + w1*r3;
            }
        }
        int glb = (tB*2 + t)*4096 + (h0 + hl)*64 + wB*4;
        outg[(size_t)(glb+0)*CC + c] = a0;
        outg[(size_t)(glb+1)*CC + c] = a1;
        outg[(size_t)(glb+2)*CC + c] = a2;
        outg[(size_t)(glb+3)*CC + c] = a3;
    }
}

// ==================================================================
// Kernel 2: windowed attention, out += softmax(q k^T * scale) @ v
// grid: 512 ; block: 256 (8 warps); 2 CTAs/SM.
// Unnormalized p = 2^s softmax; 2-strip pairing (1 LDS per mma).
// R15: unroll-1 kb loop + running-pointer addressing + per-strip
// ex2->PV ordering to fit under the 128-reg occ-2 ceiling w/o spills.
// ==================================================================
__global__ void __launch_bounds__(256, 2)
attn_kernel(const float* __restrict__ qkv, float* __restrict__ out)
{
    extern __shared__ unsigned smem[];
    unsigned* sK  = smem + SK_OFF;
    unsigned* sVt = smem + SVT_OFF;
    __nv_bfloat16* sVth = (__nv_bfloat16*)sVt;   // element (d,n) at [d*520 + n]

    const int widx = blockIdx.x >> 2;
    const int head = blockIdx.x & 3;
    const int b  = widx >> 6;
    const int tB = (widx >> 4) & 3;
    const int wB = widx & 15;
    const int ch0 = head * HD;

    const size_t plane = (size_t)BB * LL * CC;
    const float* qg = qkv + (size_t)b * LL * CC;
    const float* kg = qg + plane;
    const float* vg = qg + 2*plane;

    const int tid = threadIdx.x;

    // -------- stage K (tf32) and V (bf16 transposed) --------
    {
        const int sub  = tid & 7;    // 8 threads per token (float4)
        const int trow = tid >> 3;   // 32 tokens per iteration
        for (int it = 0; it < 16; ++it) {
            int n  = it*32 + trow;
            int gl = token_to_l(n, tB, wB);
            size_t base = (size_t)gl*CC + ch0 + sub*4;
            float4 kv = *(const float4*)(kg + base);
            float4 vv = *(const float4*)(vg + base);

            unsigned* kr = sK + n*QK_STRIDE + sub*4;
            kr[0] = f2tf32(kv.x); kr[1] = f2tf32(kv.y);
            kr[2] = f2tf32(kv.z); kr[3] = f2tf32(kv.w);

            int d = sub*4;
            sVth[(d+0)*520 + n] = __float2bfloat16(vv.x);
            sVth[(d+1)*520 + n] = __float2bfloat16(vv.y);
            sVth[(d+2)*520 + n] = __float2bfloat16(vv.z);
            sVth[(d+3)*520 + n] = __float2bfloat16(vv.w);
        }
    }
    __syncthreads();

    const int lane = tid & 31;
    const int wid  = tid >> 5;
    const int gid  = lane >> 2;   // group id (row within fragment)
    const int tig  = lane & 3;    // thread in group

    const float qs = QK_SCALE * LOG2E;

    // each warp handles 2 strip-PAIRS; pair = strips (sp, sp+16)
    for (int sp = wid; sp < 16; sp += 8) {
        const int q0A = sp * 16;
        const int q0B = q0A + 256;

        // ---- Q fragments straight from gmem for both strips ----
        const float* qpA0 = qg + (size_t)token_to_l(q0A + gid,     tB, wB)*CC + ch0;
        const float* qpA1 = qg + (size_t)token_to_l(q0A + 8 + gid, tB, wB)*CC + ch0;
        const float* qpB0 = qg + (size_t)token_to_l(q0B + gid,     tB, wB)*CC + ch0;
        const float* qpB1 = qg + (size_t)token_to_l(q0B + 8 + gid, tB, wB)*CC + ch0;
        unsigned qfA[4][4], qfB[4][4];
#pragma unroll
        for (int kc = 0; kc < 4; ++kc) {
            qfA[kc][0] = f2tf32(qpA0[kc*8 + tig]     * qs);
            qfA[kc][1] = f2tf32(qpA1[kc*8 + tig]     * qs);
            qfA[kc][2] = f2tf32(qpA0[kc*8 + tig + 4] * qs);
            qfA[kc][3] = f2tf32(qpA1[kc*8 + tig + 4] * qs);
            qfB[kc][0] = f2tf32(qpB0[kc*8 + tig]     * qs);
            qfB[kc][1] = f2tf32(qpB1[kc*8 + tig]     * qs);
            qfB[kc][2] = f2tf32(qpB0[kc*8 + tig + 4] * qs);
            qfB[kc][3] = f2tf32(qpB1[kc*8 + tig + 4] * qs);
        }

        float lA0 = 0.f, lA1 = 0.f, lB0 = 0.f, lB1 = 0.f;
        float oA[4][4], oB[4][4];
#pragma unroll
        for (int dc = 0; dc < 4; ++dc)
#pragma unroll
            for (int j = 0; j < 4; ++j) { oA[dc][j] = 0.f; oB[dc][j] = 0.f; }

        // running smem pointers (advance per kb; offsets inside are constants)
        const unsigned* krun = sK + gid*QK_STRIDE + tig;        // += 16*QK_STRIDE per kb
        const unsigned* vrun = sVt + gid*VT_STRIDE + tig;       // += 8 per kb

#pragma unroll 1
        for (int kb = 0; kb < 32; ++kb) {
            float scA[2][4], scB[2][4];
#pragma unroll
            for (int nc = 0; nc < 2; ++nc)
#pragma unroll
                for (int j = 0; j < 4; ++j) { scA[nc][j] = 0.f; scB[nc][j] = 0.f; }

            // QK: each K fragment load feeds both strips' mmas
#pragma unroll
            for (int kc = 0; kc < 4; ++kc) {
#pragma unroll
                for (int nc = 0; nc < 2; ++nc) {
                    const unsigned* kp = krun + nc*(8*QK_STRIDE) + kc*8;
                    unsigned k0 = kp[0], k1 = kp[4];
                    mma_tf32(scA[nc], qfA[kc], k0, k1);
                    mma_tf32(scB[nc], qfB[kc], k0, k1);
                }
            }

            // strip A: p = 2^s, pack, PV  (short p live range)
            {
                unsigned p01[2], p23[2];
#pragma unroll
                for (int nc = 0; nc < 2; ++nc) {
                    float e0 = ex2f(scA[nc][0]);
                    float e1 = ex2f(scA[nc][1]);
                    float e2 = ex2f(scA[nc][2]);
                    float e3 = ex2f(scA[nc][3]);
                    lA0 += e0 + e1; lA1 += e2 + e3;
                    p01[nc] = pack_bf16x2(e0, e1);
                    p23[nc] = pack_bf16x2(e2, e3);
                }
#pragma unroll
                for (int dc = 0; dc < 4; ++dc) {
                    const unsigned* vp = vrun + dc*(8*VT_STRIDE);
                    mma_bf16(oA[dc], p01[0], p23[0], p01[1], p23[1], vp[0], vp[4]);
                }
            }

            // strip B: p = 2^s, pack, PV
            {
                unsigned p01[2], p23[2];
#pragma unroll
                for (int nc = 0; nc < 2; ++nc) {
                    float e0 = ex2f(scB[nc][0]);
                    float e1 = ex2f(scB[nc][1]);
                    float e2 = ex2f(scB[nc][2]);
                    float e3 = ex2f(scB[nc][3]);
                    lB0 += e0 + e1; lB1 += e2 + e3;
                    p01[nc] = pack_bf16x2(e0, e1);
                    p23[nc] = pack_bf16x2(e2, e3);
                }
#pragma unroll
                for (int dc = 0; dc < 4; ++dc) {
                    const unsigned* vp = vrun + dc*(8*VT_STRIDE);
                    mma_bf16(oB[dc], p01[0], p23[0], p01[1], p23[1], vp[0], vp[4]);
                }
            }

            krun += 16*QK_STRIDE;
            vrun += 8;
        }

        // ---- deferred row-sum reductions ----
        lA0 += __shfl_xor_sync(0xffffffffu, lA0, 1);
        lA0 += __shfl_xor_sync(0xffffffffu, lA0, 2);
        lA1 += __shfl_xor_sync(0xffffffffu, lA1, 1);
        lA1 += __shfl_xor_sync(0xffffffffu, lA1, 2);
        lB0 += __shfl_xor_sync(0xffffffffu, lB0, 1);
        lB0 += __shfl_xor_sync(0xffffffffu, lB0, 2);
        lB1 += __shfl_xor_sync(0xffffffffu, lB1, 1);
        lB1 += __shfl_xor_sync(0xffffffffu, lB1, 2);

        // ---- epilogue: out += O / l  (out already holds lepe) ----
        float* outb = out + (size_t)b*LL*CC;
        {
            float inv0 = 1.0f / lA0, inv1 = 1.0f / lA1;
            float* op0 = outb + (size_t)token_to_l(q0A + gid,     tB, wB)*CC + ch0;
            float* op1 = outb + (size_t)token_to_l(q0A + 8 + gid, tB, wB)*CC + ch0;
#pragma unroll
            for (int dc = 0; dc < 4; ++dc) {
                int d = dc*8 + 2*tig;
                float2 u0 = *(float2*)(op0 + d);
                u0.x += oA[dc][0]*inv0; u0.y += oA[dc][1]*inv0;
                *(float2*)(op0 + d) = u0;
                float2 u1 = *(float2*)(op1 + d);
                u1.x += oA[dc][2]*inv1; u1.y += oA[dc][3]*inv1;
                *(float2*)(op1 + d) = u1;
            }
        }
        {
            float inv0 = 1.0f / lB0, inv1 = 1.0f / lB1;
            float* op0 = outb + (size_t)token_to_l(q0B + gid,     tB, wB)*CC + ch0;
            float* op1 = outb + (size_t)token_to_l(q0B + 8 + gid, tB, wB)*CC + ch0;
#pragma unroll
            for (int dc = 0; dc < 4; ++dc) {
                int d = dc*8 + 2*tig;
                float2 u0 = *(float2*)(op0 + d);
                u0.x += oB[dc][0]*inv0; u0.y += oB[dc][1]*inv0;
                *(float2*)(op0 + d) = u0;
                float2 u1 = *(float2*)(op1 + d);
                u1.x += oB[dc][2]*inv1; u1.y += oB[dc][3]*inv1;
                *(float2*)(op1 + d) = u1;
            }
        }
    }
}

// ==================================================================
extern "C" void kernel_launch(void* const* d_in, const int* in_sizes, int n_in,
                              void* d_out, int out_size)
{
    const float* qkv = (const float*)d_in[0];
    const float* lw  = (const float*)d_in[1];
    const float* lb  = (const float*)d_in[2];
    float* out = (float*)d_out;

    cudaFuncSetAttribute(lepe_kernel, cudaFuncAttributeMaxDynamicSharedMemorySize, LEPE_SMEM_BYTES);
    cudaFuncSetAttribute(attn_kernel, cudaFuncAttributeMaxDynamicSharedMemorySize, ATTN_SMEM_BYTES);

    lepe_kernel<<<NWIN*8, 256, LEPE_SMEM_BYTES>>>(qkv, lw, lb, out);
    attn_kernel<<<NWIN*NHEAD, 256, ATTN_SMEM_BYTES>>>(qkv, out);
}

// round 17
// speedup vs baseline: 1.2633x; 1.2633x over previous
#include <cuda_runtime.h>
#include <cuda_bf16.h>

// ---------------- static problem config ----------------
#define BB     2
#define TT     8
#define HHH    64
#define WWW    64
#define CC     128
#define LL     (TT*HHH*WWW)        // 32768
#define NHEAD  4
#define HD     32
#define NTOK   512                 // tokens per window
#define NWIN   128
#define QK_SCALE 0.17677669529663687f   // 1/sqrt(32)
#define LOG2E    1.4426950408889634f

// ---------------- attention smem layout (u32 units) ----------------
// K stored as fp16 pairs: row = token, 16 u32 words (32 d) + 4 pad.
// stride 20 ≡ 4 (mod 32); fragment banks (20*gid + tig) mod 32 all distinct.
#define KH_STRIDE 20
#define SK_OFF    0
#define VT_STRIDE 260                       // u32 words per d-row (256 pairs + pad)
#define SVT_OFF   (NTOK*KH_STRIDE)          // 10240
#define SMEM_U32  (SVT_OFF + 32*VT_STRIDE)  // 18560
#define ATTN_SMEM_BYTES (SMEM_U32*4)        // 74240 -> 2 CTAs/SM (regs bind)

// ---------------- helpers ----------------
__device__ __forceinline__ float ex2f(float x) {
    float r; asm("ex2.approx.ftz.f32 %0, %1;" : "=f"(r) : "f"(x)); return r;
}
__device__ __forceinline__ unsigned pack_bf16x2(float lo, float hi) {
    unsigned r; asm("cvt.rn.bf16x2.f32 %0, %1, %2;" : "=r"(r) : "f"(hi), "f"(lo)); return r;
}
__device__ __forceinline__ unsigned pack_f16x2(float lo, float hi) {
    unsigned r; asm("cvt.rn.f16x2.f32 %0, %1, %2;" : "=r"(r) : "f"(hi), "f"(lo)); return r;
}
// m16n8k16 f16 (QK^T): A=Q row-major, B=K^T col-major, fp32 accum
__device__ __forceinline__ void mma_f16(float c[4], const unsigned a[4], unsigned b0, unsigned b1) {
    asm volatile(
        "mma.sync.aligned.m16n8k16.row.col.f32.f16.f16.f32 "
        "{%0,%1,%2,%3},{%4,%5,%6,%7},{%8,%9},{%0,%1,%2,%3};"
        : "+f"(c[0]), "+f"(c[1]), "+f"(c[2]), "+f"(c[3])
        : "r"(a[0]), "r"(a[1]), "r"(a[2]), "r"(a[3]), "r"(b0), "r"(b1));
}
__device__ __forceinline__ void mma_bf16(float c[4], unsigned a0, unsigned a1, unsigned a2, unsigned a3,
                                         unsigned b0, unsigned b1) {
    asm volatile(
        "mma.sync.aligned.m16n8k16.row.col.f32.bf16.bf16.f32 "
        "{%0,%1,%2,%3},{%4,%5,%6,%7},{%8,%9},{%0,%1,%2,%3};"
        : "+f"(c[0]), "+f"(c[1]), "+f"(c[2]), "+f"(c[3])
        : "r"(a0), "r"(a1), "r"(a2), "r"(a3), "r"(b0), "r"(b1));
}

// token n in window -> flattened l (given window coords tB, wB)
__device__ __forceinline__ int token_to_l(int n, int tB, int wB) {
    int t_sp = n >> 8;
    int h_sp = (n >> 2) & 63;
    int w_sp = n & 3;
    return (tB*2 + t_sp)*4096 + h_sp*64 + wB*4 + w_sp;
}

// ==================================================================
// Kernel 1: LePE depthwise conv3d  ->  out = lepe (final layout)
// grid: 1024 = 128 windows x 8 h-tiles (8 rows each) ; block: 256
// ==================================================================
#define LP_HT     8                          // h rows per tile
#define LP_SV_F   (2*(LP_HT+2)*4*128)        // 10240 floats
#define LEPE_SMEM_BYTES ((LP_SV_F + 128*27 + 128)*4)   // 55296

__global__ void __launch_bounds__(256, 4)
lepe_kernel(const float* __restrict__ qkv, const float* __restrict__ wts,
            const float* __restrict__ bias, float* __restrict__ out)
{
    extern __shared__ float smf[];
    float* sv = smf;                 // [t=2][hh=10][w=4][c=128]
    float* sw = smf + LP_SV_F;       // [128][27]
    float* sb = sw + 128*27;         // [128]

    const int widx = blockIdx.x >> 3;
    const int tile = blockIdx.x & 7;
    const int b  = widx >> 6;
    const int tB = (widx >> 4) & 3;
    const int wB = widx & 15;
    const int h0 = tile * LP_HT;
    const int tid = threadIdx.x;

    const float* vg = qkv + 2*(size_t)BB*LL*CC + (size_t)b*LL*CC;

    for (int i = tid; i < 128*27; i += 256) sw[i] = wts[i];
    if (tid < 128) sb[tid] = bias[tid];

    // stage v tile (80 rows: t{2} x hh{10 w/ halo} x w{4}, zero pad)
    {
        int sub = tid & 31;     // float4 within a 128-float row
        int rr  = tid >> 5;     // 8 rows per iteration
        for (int r = rr; r < 2*(LP_HT+2)*4; r += 8) {
            int t   = r / ((LP_HT+2)*4);
            int rem = r % ((LP_HT+2)*4);
            int hh  = rem >> 2;
            int w   = rem & 3;
            int h   = h0 - 1 + hh;
            float4 val = make_float4(0.f, 0.f, 0.f, 0.f);
            if ((unsigned)h < 64u) {
                int gl = (tB*2 + t)*4096 + h*64 + wB*4 + w;
                val = *(const float4*)(vg + (size_t)gl*CC + sub*4);
            }
            *(float4*)(sv + (size_t)r*128 + sub*4) = val;
        }
    }
    __syncthreads();

    const int c = tid & 127;
    const int t = tid >> 7;          // each half-block owns one t slice
    float wr[27];
#pragma unroll
    for (int j = 0; j < 27; ++j) wr[j] = sw[c*27 + j];
    const float bval = sb[c];

    float* outg = out + (size_t)b*LL*CC;

    for (int hl = 0; hl < LP_HT; ++hl) {
        float a0 = bval, a1 = bval, a2 = bval, a3 = bval;
#pragma unroll
        for (int dt = 0; dt < 3; ++dt) {
            int tt = t + dt - 1;
            if ((unsigned)tt >= 2u) continue;
#pragma unroll
            for (int dh = 0; dh < 3; ++dh) {
                const float* base = sv + ((size_t)(tt*(LP_HT+2) + hl + dh)*4)*128 + c;
                float r0 = base[0], r1 = base[128], r2 = base[256], r3 = base[384];
                float w0 = wr[(dt*3+dh)*3+0], w1 = wr[(dt*3+dh)*3+1], w2 = wr[(dt*3+dh)*3+2];
                a0 += w1*r0 + w2*r1;
                a1 += w0*r0 + w1*r1 + w2*r2;
                a2 += w0*r1 + w1*r2 + w2*r3;
                a3 += w0*r2 + w1*r3;
            }
        }
        int glb = (tB*2 + t)*4096 + (h0 + hl)*64 + wB*4;
        outg[(size_t)(glb+0)*CC + c] = a0;
        outg[(size_t)(glb+1)*CC + c] = a1;
        outg[(size_t)(glb+2)*CC + c] = a2;
        outg[(size_t)(glb+3)*CC + c] = a3;
    }
}

// ==================================================================
// Kernel 2: windowed attention, out += softmax(q k^T * scale) @ v
// grid: 512 ; block: 256 (8 warps); 2 CTAs/SM.
// Unnormalized p = 2^s softmax; 2-strip pairing (1 LDS per mma).
// QK in fp16 m16n8k16 (fp16 mantissa == tf32 mantissa) —
// halves QK mma count (tensor floor 42->28us) and K LDS traffic.
// K stored fp16-pair rows stride 20 (conflict-free fragments).
// ==================================================================
__global__ void __launch_bounds__(256, 2)
attn_kernel(const float* __restrict__ qkv, float* __restrict__ out)
{
    extern __shared__ unsigned smem[];
    unsigned* sK  = smem + SK_OFF;       // fp16 pairs [token][20]
    unsigned* sVt = smem + SVT_OFF;
    __nv_bfloat16* sVth = (__nv_bfloat16*)sVt;   // element (d,n) at [d*520 + n]

    const int widx = blockIdx.x >> 2;
    const int head = blockIdx.x & 3;
    const int b  = widx >> 6;
    const int tB = (widx >> 4) & 3;
    const int wB = widx & 15;
    const int ch0 = head * HD;

    const size_t plane = (size_t)BB * LL * CC;
    const float* qg = qkv + (size_t)b * LL * CC;
    const float* kg = qg + plane;
    const float* vg = qg + 2*plane;

    const int tid = threadIdx.x;

    // -------- stage K (fp16 pairs) and V (bf16 transposed) --------
    {
        const int sub  = tid & 7;    // 8 threads per token (float4)
        const int trow = tid >> 3;   // 32 tokens per iteration
        for (int it = 0; it < 16; ++it) {
            int n  = it*32 + trow;
            int gl = token_to_l(n, tB, wB);
            size_t base = (size_t)gl*CC + ch0 + sub*4;
            float4 kv = *(const float4*)(kg + base);
            float4 vv = *(const float4*)(vg + base);

            unsigned* kr = sK + n*KH_STRIDE + sub*2;
            kr[0] = pack_f16x2(kv.x, kv.y);
            kr[1] = pack_f16x2(kv.z, kv.w);

            int d = sub*4;
            sVth[(d+0)*520 + n] = __float2bfloat16(vv.x);
            sVth[(d+1)*520 + n] = __float2bfloat16(vv.y);
            sVth[(d+2)*520 + n] = __float2bfloat16(vv.z);
            sVth[(d+3)*520 + n] = __float2bfloat16(vv.w);
        }
    }
    __syncthreads();

    const int lane = tid & 31;
    const int wid  = tid >> 5;
    const int gid  = lane >> 2;   // group id (row within fragment)
    const int tig  = lane & 3;    // thread in group

    const float qs = QK_SCALE * LOG2E;

    // each warp handles 2 strip-PAIRS; pair = strips (sp, sp+16)
    for (int sp = wid; sp < 16; sp += 8) {
        const int q0A = sp * 16;
        const int q0B = q0A + 256;

        // ---- Q fragments (fp16 pairs) straight from gmem ----
        const float* qpA0 = qg + (size_t)token_to_l(q0A + gid,     tB, wB)*CC + ch0;
        const float* qpA1 = qg + (size_t)token_to_l(q0A + 8 + gid, tB, wB)*CC + ch0;
        const float* qpB0 = qg + (size_t)token_to_l(q0B + gid,     tB, wB)*CC + ch0;
        const float* qpB1 = qg + (size_t)token_to_l(q0B + 8 + gid, tB, wB)*CC + ch0;
        unsigned qfA[2][4], qfB[2][4];
#pragma unroll
        for (int kc = 0; kc < 2; ++kc) {
            // a0: row gid, cols 16kc+2tig..+1 ; a1: row gid+8 ; a2/a3: cols +8
            float2 fA0 = *(const float2*)(qpA0 + kc*16 + 2*tig);
            float2 fA1 = *(const float2*)(qpA1 + kc*16 + 2*tig);
            float2 fA2 = *(const float2*)(qpA0 + kc*16 + 2*tig + 8);
            float2 fA3 = *(const float2*)(qpA1 + kc*16 + 2*tig + 8);
            qfA[kc][0] = pack_f16x2(fA0.x*qs, fA0.y*qs);
            qfA[kc][1] = pack_f16x2(fA1.x*qs, fA1.y*qs);
            qfA[kc][2] = pack_f16x2(fA2.x*qs, fA2.y*qs);
            qfA[kc][3] = pack_f16x2(fA3.x*qs, fA3.y*qs);
            float2 fB0 = *(const float2*)(qpB0 + kc*16 + 2*tig);
            float2 fB1 = *(const float2*)(qpB1 + kc*16 + 2*tig);
            float2 fB2 = *(const float2*)(qpB0 + kc*16 + 2*tig + 8);
            float2 fB3 = *(const float2*)(qpB1 + kc*16 + 2*tig + 8);
            qfB[kc][0] = pack_f16x2(fB0.x*qs, fB0.y*qs);
            qfB[kc][1] = pack_f16x2(fB1.x*qs, fB1.y*qs);
            qfB[kc][2] = pack_f16x2(fB2.x*qs, fB2.y*qs);
            qfB[kc][3] = pack_f16x2(fB3.x*qs, fB3.y*qs);
        }

        float lA0 = 0.f, lA1 = 0.f, lB0 = 0.f, lB1 = 0.f;
        float oA[4][4], oB[4][4];
#pragma unroll
        for (int dc = 0; dc < 4; ++dc)
#pragma unroll
            for (int j = 0; j < 4; ++j) { oA[dc][j] = 0.f; oB[dc][j] = 0.f; }

        // running smem pointers
        const unsigned* krun = sK + gid*KH_STRIDE + tig;   // += 16*KH_STRIDE per kb
        const unsigned* vrun = sVt + gid*VT_STRIDE + tig;  // += 8 per kb

#pragma unroll 1
        for (int kb = 0; kb < 32; ++kb) {
            float scA[2][4], scB[2][4];
#pragma unroll
            for (int nc = 0; nc < 2; ++nc)
#pragma unroll
                for (int j = 0; j < 4; ++j) { scA[nc][j] = 0.f; scB[nc][j] = 0.f; }

            // QK (fp16, k=16/mma): each K fragment load feeds both strips
#pragma unroll
            for (int kc = 0; kc < 2; ++kc) {
#pragma unroll
                for (int nc = 0; nc < 2; ++nc) {
                    const unsigned* kp = krun + nc*(8*KH_STRIDE) + kc*8;
                    unsigned k0 = kp[0], k1 = kp[4];
                    mma_f16(scA[nc], qfA[kc], k0, k1);
                    mma_f16(scB[nc], qfB[kc], k0, k1);
                }
            }

            // strip A: p = 2^s, pack, PV
            {
                unsigned p01[2], p23[2];
#pragma unroll
                for (int nc = 0; nc < 2; ++nc) {
                    float e0 = ex2f(scA[nc][0]);
                    float e1 = ex2f(scA[nc][1]);
                    float e2 = ex2f(scA[nc][2]);
                    float e3 = ex2f(scA[nc][3]);
                    lA0 += e0 + e1; lA1 += e2 + e3;
                    p01[nc] = pack_bf16x2(e0, e1);
                    p23[nc] = pack_bf16x2(e2, e3);
                }
#pragma unroll
                for (int dc = 0; dc < 4; ++dc) {
                    const unsigned* vp = vrun + dc*(8*VT_STRIDE);
                    mma_bf16(oA[dc], p01[0], p23[0], p01[1], p23[1], vp[0], vp[4]);
                }
            }

            // strip B: p = 2^s, pack, PV
            {
                unsigned p01[2], p23[2];
#pragma unroll
                for (int nc = 0; nc < 2; ++nc) {
                    float e0 = ex2f(scB[nc][0]);
                    float e1 = ex2f(scB[nc][1]);
                    float e2 = ex2f(scB[nc][2]);
                    float e3 = ex2f(scB[nc][3]);
                    lB0 += e0 + e1; lB1 += e2 + e3;
                    p01[nc] = pack_bf16x2(e0, e1);
                    p23[nc] = pack_bf16x2(e2, e3);
                }
#pragma unroll
                for (int dc = 0; dc < 4; ++dc) {
                    const unsigned* vp = vrun + dc*(8*VT_STRIDE);
                    mma_bf16(oB[dc], p01[0], p23[0], p01[1], p23[1], vp[0], vp[4]);
                }
            }

            krun += 16*KH_STRIDE;
            vrun += 8;
        }

        // ---- deferred row-sum reductions ----
        lA0 += __shfl_xor_sync(0xffffffffu, lA0, 1);
        lA0 += __shfl_xor_sync(0xffffffffu, lA0, 2);
        lA1 += __shfl_xor_sync(0xffffffffu, lA1, 1);
        lA1 += __shfl_xor_sync(0xffffffffu, lA1, 2);
        lB0 += __shfl_xor_sync(0xffffffffu, lB0, 1);
        lB0 += __shfl_xor_sync(0xffffffffu, lB0, 2);
        lB1 += __shfl_xor_sync(0xffffffffu, lB1, 1);
        lB1 += __shfl_xor_sync(0xffffffffu, lB1, 2);

        // ---- epilogue: out += O / l  (out already holds lepe) ----
        float* outb = out + (size_t)b*LL*CC;
        {
            float inv0 = 1.0f / lA0, inv1 = 1.0f / lA1;
            float* op0 = outb + (size_t)token_to_l(q0A + gid,     tB, wB)*CC + ch0;
            float* op1 = outb + (size_t)token_to_l(q0A + 8 + gid, tB, wB)*CC + ch0;
#pragma unroll
            for (int dc = 0; dc < 4; ++dc) {
                int d = dc*8 + 2*tig;
                float2 u0 = *(float2*)(op0 + d);
                u0.x += oA[dc][0]*inv0; u0.y += oA[dc][1]*inv0;
                *(float2*)(op0 + d) = u0;
                float2 u1 = *(float2*)(op1 + d);
                u1.x += oA[dc][2]*inv1; u1.y += oA[dc][3]*inv1;
                *(float2*)(op1 + d) = u1;
            }
        }
        {
            float inv0 = 1.0f / lB0, inv1 = 1.0f / lB1;
            float* op0 = outb + (size_t)token_to_l(q0B + gid,     tB, wB)*CC + ch0;
            float* op1 = outb + (size_t)token_to_l(q0B + 8 + gid, tB, wB)*CC + ch0;
#pragma unroll
            for (int dc = 0; dc < 4; ++dc) {
                int d = dc*8 + 2*tig;
                float2 u0 = *(float2*)(op0 + d);
                u0.x += oB[dc][0]*inv0; u0.y += oB[dc][1]*inv0;
                *(float2*)(op0 + d) = u0;
                float2 u1 = *(float2*)(op1 + d);
                u1.x += oB[dc][2]*inv1; u1.y += oB[dc][3]*inv1;
                *(float2*)(op1 + d) = u1;
            }
        }
    }
}

// ==================================================================
extern "C" void kernel_launch(void* const* d_in, const int* in_sizes, int n_in,
                              void* d_out, int out_size)
{
    const float* qkv = (const float*)d_in[0];
    const float* lw  = (const float*)d_in[1];
    const float* lb  = (const float*)d_in[2];
    float* out = (float*)d_out;

    cudaFuncSetAttribute(lepe_kernel, cudaFuncAttributeMaxDynamicSharedMemorySize, LEPE_SMEM_BYTES);
    cudaFuncSetAttribute(attn_kernel, cudaFuncAttributeMaxDynamicSharedMemorySize, ATTN_SMEM_BYTES);

    lepe_kernel<<<NWIN*8, 256, LEPE_SMEM_BYTES>>>(qkv, lw, lb, out);
    attn_kernel<<<NWIN*NHEAD, 256, ATTN_SMEM_BYTES>>>(qkv, out);
}